// round 4
// baseline (speedup 1.0000x reference)
#include <cuda_runtime.h>
#include <cuda_bf16.h>
#include <cstdint>

#define Bn 128
#define Qn 200
#define Cn 92
#define NT 256
#define FINF 1e9f
#define ARR_CAP 1000

struct Smem {
    float cost[Qn * Qn];   // cost[i*Qn + j]
    float v[Qn];           // column potentials
    int   y[Qn];           // y[j] = row matched to column j, -1 free
    int   x[Qn];           // x[i] = col matched to row i,    -1 free
    int   predsm[Qn];      // back-pointers (dumped before augment walk)
    int   frees[Qn + 8];   // free-row worklist
    int   s_cur, s_cnt;
    int   tc[Qn];
    float lse[Qn];
    float pb[Qn * 4];
    float tb[Qn * 4];
    unsigned long long pair1[8], pair2[8];  // ARR per-warp (min1,min2) slots
    unsigned rk[2][8];     // Dijkstra per-warp argmin key (parity-buffered)
    int      rc[2][8];
};

__device__ __forceinline__ unsigned fkey(float f) {
    unsigned b = __float_as_uint(f);
    return (b & 0x80000000u) ? ~b : (b | 0x80000000u);
}
__device__ __forceinline__ float keyf(unsigned k) {
    unsigned b = (k & 0x80000000u) ? (k & 0x7fffffffu) : ~k;
    return __uint_as_float(b);
}

__global__ __launch_bounds__(NT, 1)
void hungarian_loss_kernel(const float* __restrict__ pred_cat,
                           const float* __restrict__ pred_bbox,
                           const int*   __restrict__ tar_cat,
                           const float* __restrict__ tar_bbox,
                           float* __restrict__ out) {
    extern __shared__ char smem_raw[];
    Smem* sm = reinterpret_cast<Smem*>(smem_raw);

    const int b    = blockIdx.x;
    const int tid  = threadIdx.x;
    const int lane = tid & 31;
    const int wid  = tid >> 5;

    // ---------------- Phase A: stage small tensors + per-row logsumexp ------
    if (tid == 0) { sm->s_cur = 0; sm->s_cnt = 0; }
    for (int i = tid; i < Qn; i += NT) { sm->tc[i] = tar_cat[b * Qn + i]; sm->x[i] = -1; sm->y[i] = -1; }
    for (int i = tid; i < Qn * 4; i += NT) {
        sm->pb[i] = pred_bbox[(size_t)b * Qn * 4 + i];
        sm->tb[i] = tar_bbox[(size_t)b * Qn * 4 + i];
    }
    for (int row = wid; row < Qn; row += (NT / 32)) {
        const float* xr = pred_cat + ((size_t)b * Qn + row) * Cn;
        float m = -FINF;
        for (int c = lane; c < Cn; c += 32) m = fmaxf(m, xr[c]);
        #pragma unroll
        for (int o = 16; o; o >>= 1) m = fmaxf(m, __shfl_xor_sync(0xFFFFFFFFu, m, o));
        float s = 0.f;
        for (int c = lane; c < Cn; c += 32) s += expf(xr[c] - m);
        #pragma unroll
        for (int o = 16; o; o >>= 1) s += __shfl_xor_sync(0xFFFFFFFFu, s, o);
        if (lane == 0) sm->lse[row] = m + logf(s);
    }
    __syncthreads();

    // ---------------- Phase B: cost matrix into smem ------------------------
    for (int idx = tid; idx < Qn * Qn; idx += NT) {
        const int i = idx / Qn;
        const int j = idx - i * Qn;
        const int cls = sm->tc[j];
        const float ce = sm->lse[i] - pred_cat[((size_t)b * Qn + i) * Cn + cls];
        float sl1 = 0.f;
        #pragma unroll
        for (int k = 0; k < 4; k++) {
            const float d  = sm->pb[i * 4 + k] - sm->tb[j * 4 + k];
            const float ad = fabsf(d);
            sl1 += (ad < 1.f) ? 0.5f * d * d : (ad - 0.5f);
        }
        const float mask = (cls != 0) ? 1.f : 0.f;
        sm->cost[idx] = ce + sl1 * mask;
    }
    __syncthreads();

    // ---------------- Phase C1: column reduction + greedy tight match -------
    if (tid < Qn) {
        float mn = FINF; int ia = 0;
        for (int i = 0; i < Qn; i++) {
            const float val = sm->cost[i * Qn + tid];
            if (val < mn) { mn = val; ia = i; }
        }
        sm->v[tid] = mn;
        if (atomicCAS(&sm->x[ia], -1, tid) == -1) sm->y[tid] = ia;
    }
    __syncthreads();
    if (tid < Qn && sm->x[tid] == -1) {
        const int pos = atomicAdd(&sm->s_cnt, 1);
        sm->frees[pos] = tid;
    }
    __syncthreads();

    // ---------------- Phase C1b: Augmenting Row Reduction (LAPJV) -----------
    // Each step: free row i, (min1,j1,min2,j2) of reduced row, v[j1] -= min2-min1,
    // claim column; displaced row re-enters the list. Invariants (dual feasible,
    // matched edges tight) hold after ANY prefix -> safe to cap iterations.
    {
        int iters = 0;
        for (;;) {
            const int cur = sm->s_cur;
            const int cnt = sm->s_cnt;
            if (cur >= cnt || iters >= ARR_CAP) break;
            iters++;
            const int i = sm->frees[cur];

            // per-lane packed (key<<32 | col); pair = two smallest
            unsigned long long a1 = ~0ull, a2 = ~0ull;
            if (tid < Qn) {
                const float r = sm->cost[i * Qn + tid] - sm->v[tid];
                a1 = ((unsigned long long)fkey(r) << 32) | (unsigned)tid;
            }
            #pragma unroll
            for (int o = 16; o; o >>= 1) {
                const unsigned long long b1 = __shfl_xor_sync(0xFFFFFFFFu, a1, o);
                const unsigned long long b2 = __shfl_xor_sync(0xFFFFFFFFu, a2, o);
                const unsigned long long lo = (a1 < b1) ? a1 : b1;
                const unsigned long long hi = (a1 < b1) ? b1 : a1;
                const unsigned long long mn2 = (a2 < b2) ? a2 : b2;
                a1 = lo;
                a2 = (hi < mn2) ? hi : mn2;
            }
            if (lane == 0) { sm->pair1[wid] = a1; sm->pair2[wid] = a2; }
            __syncthreads();                    // (1) slots ready

            if (tid == 0) {
                unsigned long long m1 = ~0ull, m2 = ~0ull;
                #pragma unroll
                for (int w = 0; w < 8; w++) {
                    const unsigned long long b1 = sm->pair1[w];
                    const unsigned long long b2 = sm->pair2[w];
                    const unsigned long long lo = (m1 < b1) ? m1 : b1;
                    const unsigned long long hi = (m1 < b1) ? b1 : m1;
                    const unsigned long long mn2 = (m2 < b2) ? m2 : b2;
                    m1 = lo;
                    m2 = (hi < mn2) ? hi : mn2;
                }
                const unsigned k1 = (unsigned)(m1 >> 32);
                const unsigned k2 = (unsigned)(m2 >> 32);
                int jt = (int)(unsigned)m1;          // j1
                const bool strict = (k1 < k2);
                int i0 = sm->y[jt];
                if (strict) {
                    sm->v[jt] -= keyf(k2) - keyf(k1);
                } else if (i0 >= 0) {
                    jt = (int)(unsigned)m2;          // tie: take j2 instead
                    i0 = sm->y[jt];
                }
                sm->x[i] = jt;
                sm->y[jt] = i;
                int ncur = cur + 1, ncnt = cnt;
                if (i0 >= 0) {
                    if (strict) { ncur--; sm->frees[ncur] = i0; }   // immediate retry
                    else        { sm->frees[ncnt++] = i0; }         // append
                }
                sm->s_cur = ncur;
                sm->s_cnt = ncnt;
            }
            __syncthreads();                    // (2) v,y,x,frees,cursors visible
        }
    }

    const int fcur = sm->s_cur;
    const int fcnt = sm->s_cnt;

    // ---------------- Phase C2: JV shortest-path for remaining frees --------
    for (int fi = fcur; fi < fcnt; fi++) {
        const int f = sm->frees[fi];

        float d    = FINF;
        int   pred = f;
        bool  todo = (tid < Qn);
        if (todo) d = sm->cost[f * Qn + tid] - sm->v[tid];

        int   t = 0;
        int   jsel;
        float dfin;

        for (;;) {
            const unsigned key  = todo ? fkey(d) : 0xFFFFFFFFu;
            const unsigned rmin = __reduce_min_sync(0xFFFFFFFFu, key);
            const unsigned ball = __ballot_sync(0xFFFFFFFFu, key == rmin);
            if (lane == 0) {
                sm->rk[t][wid] = rmin;
                sm->rc[t][wid] = (rmin == 0xFFFFFFFFu) ? 0x7fffffff
                                                       : (wid * 32 + (__ffs(ball) - 1));
            }
            __syncthreads();                      // only barrier per pop

            unsigned bk = 0xFFFFFFFFu; int bc = 0x7fffffff;
            #pragma unroll
            for (int w = 0; w < 8; w++) {
                const unsigned kk = sm->rk[t][w];
                const int      cc = sm->rc[t][w];
                if (kk < bk || (kk == bk && cc < bc)) { bk = kk; bc = cc; }
            }
            t ^= 1;
            const float delta = keyf(bk);
            const int   jstar = bc;

            if (tid == jstar) todo = false;
            const int irow = sm->y[jstar];
            if (irow < 0) { jsel = jstar; dfin = delta; break; }

            const float h = sm->cost[irow * Qn + jstar] - sm->v[jstar] - delta;
            if (todo) {
                const float nd = sm->cost[irow * Qn + tid] - sm->v[tid] - h;
                if (nd < d) { d = nd; pred = irow; }
            }
        }

        if (tid < Qn) {
            sm->predsm[tid] = pred;
            if (!todo) sm->v[tid] += d - dfin;    // popped columns
        }
        __syncthreads();
        if (tid == 0) {
            int j = jsel;
            for (;;) {
                const int i  = sm->predsm[j];
                sm->y[j] = i;
                const int jn = sm->x[i];
                sm->x[i] = j;
                if (i == f) break;
                j = jn;
            }
        }
        __syncthreads();
    }

    // ---------------- Phase D: gather matched costs -------------------------
    for (int j = tid; j < Qn; j += NT) {
        const int row = sm->y[j];
        out[b * Qn + row] = sm->cost[row * Qn + j];
    }
}

extern "C" void kernel_launch(void* const* d_in, const int* in_sizes, int n_in,
                              void* d_out, int out_size) {
    const float* pred_cat  = (const float*)d_in[0];
    const float* pred_bbox = (const float*)d_in[1];
    const int*   tar_cat   = (const int*)d_in[2];
    const float* tar_bbox  = (const float*)d_in[3];
    float* out = (float*)d_out;

    static bool attr_set = false;
    if (!attr_set) {
        cudaFuncSetAttribute(hungarian_loss_kernel,
                             cudaFuncAttributeMaxDynamicSharedMemorySize,
                             (int)sizeof(Smem));
        attr_set = true;
    }
    hungarian_loss_kernel<<<Bn, NT, sizeof(Smem)>>>(
        pred_cat, pred_bbox, tar_cat, tar_bbox, out);
}

// round 5
// speedup vs baseline: 1.2557x; 1.2557x over previous
#include <cuda_runtime.h>
#include <cuda_bf16.h>
#include <cstdint>

#define Bn 128
#define Qn 200
#define Cn 92
#define NT 256
#define FINF 1e9f

struct Smem {
    float cost[Qn * Qn];   // cost[i*Qn + j]
    int   y[Qn];           // y[j] = row matched to column j, -1 free
    int   x[Qn];           // x[i] = col matched to row i,    -1 free
    int   predsm[Qn];      // back-pointers for augment walk
    int   frees[Qn];       // free-row worklist
    int   nfree;
    int   tc[Qn];
    float lse[Qn];
    float pb[Qn * 4];
    float tb[Qn * 4];
    uint4 slots[2][8];     // per-warp {key, col, irow, e_bits}, parity-buffered
};

// monotone float<->uint key (order preserved under unsigned compare)
__device__ __forceinline__ unsigned fkey(float f) {
    unsigned b = __float_as_uint(f);
    return (b & 0x80000000u) ? ~b : (b | 0x80000000u);
}
__device__ __forceinline__ float keyf(unsigned k) {
    unsigned b = (k & 0x80000000u) ? (k & 0x7fffffffu) : ~k;
    return __uint_as_float(b);
}
// (key, col) lexicographic min on uint4 slots
__device__ __forceinline__ void umin4(uint4& a, const uint4& b) {
    if (b.x < a.x || (b.x == a.x && b.y < a.y)) a = b;
}

__global__ __launch_bounds__(NT, 1)
void hungarian_loss_kernel(const float* __restrict__ pred_cat,
                           const float* __restrict__ pred_bbox,
                           const int*   __restrict__ tar_cat,
                           const float* __restrict__ tar_bbox,
                           float* __restrict__ out) {
    extern __shared__ char smem_raw[];
    Smem* sm = reinterpret_cast<Smem*>(smem_raw);

    const int b    = blockIdx.x;
    const int tid  = threadIdx.x;
    const int lane = tid & 31;
    const int wid  = tid >> 5;

    // ---------------- Phase A: stage small tensors + per-row logsumexp ------
    if (tid == 0) sm->nfree = 0;
    for (int i = tid; i < Qn; i += NT) { sm->tc[i] = tar_cat[b * Qn + i]; sm->x[i] = -1; sm->y[i] = -1; }
    for (int i = tid; i < Qn * 4; i += NT) {
        sm->pb[i] = pred_bbox[(size_t)b * Qn * 4 + i];
        sm->tb[i] = tar_bbox[(size_t)b * Qn * 4 + i];
    }
    for (int row = wid; row < Qn; row += (NT / 32)) {
        const float* xr = pred_cat + ((size_t)b * Qn + row) * Cn;
        float m = -FINF;
        for (int c = lane; c < Cn; c += 32) m = fmaxf(m, xr[c]);
        #pragma unroll
        for (int o = 16; o; o >>= 1) m = fmaxf(m, __shfl_xor_sync(0xFFFFFFFFu, m, o));
        float s = 0.f;
        for (int c = lane; c < Cn; c += 32) s += expf(xr[c] - m);
        #pragma unroll
        for (int o = 16; o; o >>= 1) s += __shfl_xor_sync(0xFFFFFFFFu, s, o);
        if (lane == 0) sm->lse[row] = m + logf(s);
    }
    __syncthreads();

    // ---------------- Phase B: cost matrix into smem ------------------------
    for (int idx = tid; idx < Qn * Qn; idx += NT) {
        const int i = idx / Qn;
        const int j = idx - i * Qn;
        const int cls = sm->tc[j];
        const float ce = sm->lse[i] - pred_cat[((size_t)b * Qn + i) * Cn + cls];
        float sl1 = 0.f;
        #pragma unroll
        for (int k = 0; k < 4; k++) {
            const float d  = sm->pb[i * 4 + k] - sm->tb[j * 4 + k];
            const float ad = fabsf(d);
            sl1 += (ad < 1.f) ? 0.5f * d * d : (ad - 0.5f);
        }
        const float mask = (cls != 0) ? 1.f : 0.f;
        sm->cost[idx] = ce + sl1 * mask;
    }
    __syncthreads();

    // ---------------- Phase C1: column reduction + greedy tight match -------
    // v lives in a register of its owning thread (column tid).
    float v_reg = 0.f;
    int   y_reg = -1;
    float e_reg = 0.f;     // cost[y_reg][tid] - v_reg (dual u of matched row)
    if (tid < Qn) {
        float mn = FINF; int ia = 0;
        for (int i = 0; i < Qn; i++) {
            const float val = sm->cost[i * Qn + tid];
            if (val < mn) { mn = val; ia = i; }
        }
        v_reg = mn;
        if (atomicCAS(&sm->x[ia], -1, tid) == -1) sm->y[tid] = ia;
    }
    __syncthreads();
    if (tid < Qn) {
        if (sm->x[tid] == -1) {
            const int pos = atomicAdd(&sm->nfree, 1);
            sm->frees[pos] = tid;
        }
        y_reg = sm->y[tid];                   // greedy matches are tight: e = 0
        if (y_reg >= 0) e_reg = sm->cost[y_reg * Qn + tid] - v_reg;
    }
    __syncthreads();
    const int nf = sm->nfree;

    // ---------------- Phase C2: JV shortest-path augmentation ---------------
    for (int fi = 0; fi < nf; fi++) {
        const int f = sm->frees[fi];

        float d    = FINF;
        int   pred = f;
        bool  todo = (tid < Qn);
        if (todo) d = sm->cost[f * Qn + tid] - v_reg;

        int   t = 0;
        int   jsel;
        float dfin;

        for (;;) {
            // warp argmin of d; gather winner's (col, irow, e) via shuffles
            const unsigned key  = todo ? fkey(d) : 0xFFFFFFFFu;
            const unsigned rmin = __reduce_min_sync(0xFFFFFFFFu, key);
            const unsigned ball = __ballot_sync(0xFFFFFFFFu, key == rmin);
            const int src   = __ffs(ball) - 1;
            const int wcol  = __shfl_sync(0xFFFFFFFFu, tid,   src);
            const int wirow = __shfl_sync(0xFFFFFFFFu, y_reg, src);
            const float we  = __shfl_sync(0xFFFFFFFFu, e_reg, src);
            if (lane == 0) {
                sm->slots[t][wid] = make_uint4(
                    rmin,
                    (rmin == 0xFFFFFFFFu) ? 0x7fffffffu : (unsigned)wcol,
                    (unsigned)wirow,
                    __float_as_uint(we));
            }
            __syncthreads();                      // only barrier per pop

            // block min over 8 slots: wide loads + 3-level tree
            uint4 s0 = sm->slots[t][0], s1 = sm->slots[t][1];
            uint4 s2 = sm->slots[t][2], s3 = sm->slots[t][3];
            uint4 s4 = sm->slots[t][4], s5 = sm->slots[t][5];
            uint4 s6 = sm->slots[t][6], s7 = sm->slots[t][7];
            umin4(s0, s1); umin4(s2, s3); umin4(s4, s5); umin4(s6, s7);
            umin4(s0, s2); umin4(s4, s6); umin4(s0, s4);
            t ^= 1;

            const float delta = keyf(s0.x);
            const int   jstar = (int)s0.y;
            const int   irow  = (int)s0.z;

            if (tid == jstar) todo = false;       // pop j*
            if (irow < 0) { jsel = jstar; dfin = delta; break; }

            const float h = __uint_as_float(s0.w) - delta;   // u[irow] - delta
            if (todo) {
                const float nd = sm->cost[irow * Qn + tid] - v_reg - h;
                if (nd < d) { d = nd; pred = irow; }
            }
        }

        // potentials + back-pointers, then serial augment walk
        if (tid < Qn) {
            sm->predsm[tid] = pred;
            if (!todo) v_reg += d - dfin;         // popped columns
        }
        __syncthreads();
        if (tid == 0) {
            int j = jsel;
            for (;;) {
                const int i  = sm->predsm[j];
                sm->y[j] = i;
                const int jn = sm->x[i];
                sm->x[i] = j;
                if (i == f) break;
                j = jn;
            }
        }
        __syncthreads();
        if (tid < Qn) {                           // refresh cached (y, e)
            y_reg = sm->y[tid];
            if (y_reg >= 0) e_reg = sm->cost[y_reg * Qn + tid] - v_reg;
        }
    }

    // ---------------- Phase D: gather matched costs -------------------------
    for (int j = tid; j < Qn; j += NT) {
        const int row = sm->y[j];
        out[b * Qn + row] = sm->cost[row * Qn + j];
    }
}

extern "C" void kernel_launch(void* const* d_in, const int* in_sizes, int n_in,
                              void* d_out, int out_size) {
    const float* pred_cat  = (const float*)d_in[0];
    const float* pred_bbox = (const float*)d_in[1];
    const int*   tar_cat   = (const int*)d_in[2];
    const float* tar_bbox  = (const float*)d_in[3];
    float* out = (float*)d_out;

    static bool attr_set = false;
    if (!attr_set) {
        cudaFuncSetAttribute(hungarian_loss_kernel,
                             cudaFuncAttributeMaxDynamicSharedMemorySize,
                             (int)sizeof(Smem));
        attr_set = true;
    }
    hungarian_loss_kernel<<<Bn, NT, sizeof(Smem)>>>(
        pred_cat, pred_bbox, tar_cat, tar_bbox, out);
}

// round 6
// speedup vs baseline: 1.3558x; 1.0797x over previous
#include <cuda_runtime.h>
#include <cuda_bf16.h>
#include <cstdint>

#define Bn 128
#define Qn 200
#define Cn 92
#define NT 256
#define FINF 1e9f

struct Smem {
    float cost[Qn * Qn];   // cost[i*Qn + j]
    float v[Qn];           // column potentials snapshot (old v for the pass)
    float v2[Qn];          // transferred potentials
    int   y[Qn];           // y[j] = row matched to column j, -1 free
    int   x[Qn];           // x[i] = col matched to row i,    -1 free
    int   predsm[Qn];      // back-pointers for augment walk
    int   frees[Qn];       // free-row worklist
    int   nfree;
    int   tc[Qn];
    float lse[Qn];
    float pb[Qn * 4];
    float tb[Qn * 4];
    uint4 slots[2][8];     // per-warp {key, col, irow, e_bits}, parity-buffered
};

// monotone float<->uint key (order preserved under unsigned compare)
__device__ __forceinline__ unsigned fkey(float f) {
    unsigned b = __float_as_uint(f);
    return (b & 0x80000000u) ? ~b : (b | 0x80000000u);
}
__device__ __forceinline__ float keyf(unsigned k) {
    unsigned b = (k & 0x80000000u) ? (k & 0x7fffffffu) : ~k;
    return __uint_as_float(b);
}
__device__ __forceinline__ void umin4(uint4& a, const uint4& b) {
    if (b.x < a.x || (b.x == a.x && b.y < a.y)) a = b;
}

__global__ __launch_bounds__(NT, 1)
void hungarian_loss_kernel(const float* __restrict__ pred_cat,
                           const float* __restrict__ pred_bbox,
                           const int*   __restrict__ tar_cat,
                           const float* __restrict__ tar_bbox,
                           float* __restrict__ out) {
    extern __shared__ char smem_raw[];
    Smem* sm = reinterpret_cast<Smem*>(smem_raw);

    const int b    = blockIdx.x;
    const int tid  = threadIdx.x;
    const int lane = tid & 31;
    const int wid  = tid >> 5;

    // ---------------- Phase A: stage small tensors + per-row logsumexp ------
    if (tid == 0) sm->nfree = 0;
    for (int i = tid; i < Qn; i += NT) { sm->tc[i] = tar_cat[b * Qn + i]; sm->x[i] = -1; sm->y[i] = -1; }
    for (int i = tid; i < Qn * 4; i += NT) {
        sm->pb[i] = pred_bbox[(size_t)b * Qn * 4 + i];
        sm->tb[i] = tar_bbox[(size_t)b * Qn * 4 + i];
    }
    for (int row = wid; row < Qn; row += (NT / 32)) {
        const float* xr = pred_cat + ((size_t)b * Qn + row) * Cn;
        float m = -FINF;
        for (int c = lane; c < Cn; c += 32) m = fmaxf(m, xr[c]);
        #pragma unroll
        for (int o = 16; o; o >>= 1) m = fmaxf(m, __shfl_xor_sync(0xFFFFFFFFu, m, o));
        float s = 0.f;
        for (int c = lane; c < Cn; c += 32) s += expf(xr[c] - m);
        #pragma unroll
        for (int o = 16; o; o >>= 1) s += __shfl_xor_sync(0xFFFFFFFFu, s, o);
        if (lane == 0) sm->lse[row] = m + logf(s);
    }
    __syncthreads();

    // ---------------- Phase B: cost matrix into smem ------------------------
    for (int idx = tid; idx < Qn * Qn; idx += NT) {
        const int i = idx / Qn;
        const int j = idx - i * Qn;
        const int cls = sm->tc[j];
        const float ce = sm->lse[i] - pred_cat[((size_t)b * Qn + i) * Cn + cls];
        float sl1 = 0.f;
        #pragma unroll
        for (int k = 0; k < 4; k++) {
            const float d  = sm->pb[i * 4 + k] - sm->tb[j * 4 + k];
            const float ad = fabsf(d);
            sl1 += (ad < 1.f) ? 0.5f * d * d : (ad - 0.5f);
        }
        const float mask = (cls != 0) ? 1.f : 0.f;
        sm->cost[idx] = ce + sl1 * mask;
    }
    __syncthreads();

    // ---------------- Phase C1: column reduction + greedy tight match -------
    float v_reg = 0.f;
    int   y_reg = -1;
    float e_reg = 0.f;     // u of matched row = cost[y][tid] - v[tid]
    if (tid < Qn) {
        float mn = FINF; int ia = 0;
        for (int i = 0; i < Qn; i++) {
            const float val = sm->cost[i * Qn + tid];   // banks distinct across tid
            if (val < mn) { mn = val; ia = i; }
        }
        v_reg = mn;
        if (atomicCAS(&sm->x[ia], -1, tid) == -1) sm->y[tid] = ia;
    }
    __syncthreads();
    if (tid < Qn) { sm->v[tid] = v_reg; sm->v2[tid] = v_reg; }
    __syncthreads();

    // ---------------- Phase C1b: reduction transfer + free tight claims -----
    // thread = ROW i. Matched: v[x[i]] -= min_{j != x[i]} (c[i][j]-v[j])  (lap.c).
    // Free: (min1, jmin); claim jmin if it is an unmatched column.
    if (tid < Qn) {
        const int i  = tid;
        const int j1 = sm->x[i];
        float mn = FINF; int jmin = 0;
        int jj = i;                                  // stagger: conflict-free banks
        for (int step = 0; step < Qn; step++) {
            const float r = sm->cost[i * Qn + jj] - sm->v[jj];
            if (jj != j1 && r < mn) { mn = r; jmin = jj; }
            jj++; if (jj == Qn) jj = 0;
        }
        if (j1 >= 0) {
            sm->v2[j1] = sm->v[j1] - mn;             // unique writer per column
        } else if (sm->y[jmin] == -1) {
            if (atomicCAS(&sm->y[jmin], -1, i) == -1) sm->x[i] = jmin;
        }
    }
    __syncthreads();

    // rebuild free list; reload column state
    if (tid < Qn) {
        if (sm->x[tid] == -1) {
            const int pos = atomicAdd(&sm->nfree, 1);
            sm->frees[pos] = tid;
        }
        v_reg = sm->v2[tid];
        y_reg = sm->y[tid];
        if (y_reg >= 0) e_reg = sm->cost[y_reg * Qn + tid] - v_reg;
    }
    __syncthreads();
    const int nf = sm->nfree;

    // ---------------- Phase C2: JV shortest-path augmentation ---------------
    for (int fi = 0; fi < nf; fi++) {
        const int f = sm->frees[fi];

        float d    = FINF;
        int   pred = f;
        bool  todo = (tid < Qn);
        if (todo) d = sm->cost[f * Qn + tid] - v_reg;

        int   t = 0;
        int   jsel;
        float dfin;

        for (;;) {
            const unsigned key  = todo ? fkey(d) : 0xFFFFFFFFu;
            const unsigned rmin = __reduce_min_sync(0xFFFFFFFFu, key);
            const unsigned ball = __ballot_sync(0xFFFFFFFFu, key == rmin);
            const int src   = __ffs(ball) - 1;
            const int wcol  = __shfl_sync(0xFFFFFFFFu, tid,   src);
            const int wirow = __shfl_sync(0xFFFFFFFFu, y_reg, src);
            const float we  = __shfl_sync(0xFFFFFFFFu, e_reg, src);
            if (lane == 0) {
                sm->slots[t][wid] = make_uint4(
                    rmin,
                    (rmin == 0xFFFFFFFFu) ? 0x7fffffffu : (unsigned)wcol,
                    (unsigned)wirow,
                    __float_as_uint(we));
            }
            __syncthreads();                      // only barrier per pop

            uint4 s0 = sm->slots[t][0], s1 = sm->slots[t][1];
            uint4 s2 = sm->slots[t][2], s3 = sm->slots[t][3];
            uint4 s4 = sm->slots[t][4], s5 = sm->slots[t][5];
            uint4 s6 = sm->slots[t][6], s7 = sm->slots[t][7];
            umin4(s0, s1); umin4(s2, s3); umin4(s4, s5); umin4(s6, s7);
            umin4(s0, s2); umin4(s4, s6); umin4(s0, s4);
            t ^= 1;

            const float delta = keyf(s0.x);
            const int   jstar = (int)s0.y;
            const int   irow  = (int)s0.z;

            if (tid == jstar) todo = false;       // pop j*
            if (irow < 0) { jsel = jstar; dfin = delta; break; }

            const float h = __uint_as_float(s0.w) - delta;   // u[irow] - delta
            if (todo) {
                const float nd = sm->cost[irow * Qn + tid] - v_reg - h;
                if (nd < d) { d = nd; pred = irow; }
            }
        }

        if (tid < Qn) {
            sm->predsm[tid] = pred;
            if (!todo) v_reg += d - dfin;         // popped columns
        }
        __syncthreads();
        if (tid == 0) {
            int j = jsel;
            for (;;) {
                const int i  = sm->predsm[j];
                sm->y[j] = i;
                const int jn = sm->x[i];
                sm->x[i] = j;
                if (i == f) break;
                j = jn;
            }
        }
        __syncthreads();
        if (tid < Qn) {                           // refresh cached (y, e)
            y_reg = sm->y[tid];
            if (y_reg >= 0) e_reg = sm->cost[y_reg * Qn + tid] - v_reg;
        }
    }

    // ---------------- Phase D: gather matched costs -------------------------
    for (int j = tid; j < Qn; j += NT) {
        const int row = sm->y[j];
        out[b * Qn + row] = sm->cost[row * Qn + j];
    }
}

extern "C" void kernel_launch(void* const* d_in, const int* in_sizes, int n_in,
                              void* d_out, int out_size) {
    const float* pred_cat  = (const float*)d_in[0];
    const float* pred_bbox = (const float*)d_in[1];
    const int*   tar_cat   = (const int*)d_in[2];
    const float* tar_bbox  = (const float*)d_in[3];
    float* out = (float*)d_out;

    static bool attr_set = false;
    if (!attr_set) {
        cudaFuncSetAttribute(hungarian_loss_kernel,
                             cudaFuncAttributeMaxDynamicSharedMemorySize,
                             (int)sizeof(Smem));
        attr_set = true;
    }
    hungarian_loss_kernel<<<Bn, NT, sizeof(Smem)>>>(
        pred_cat, pred_bbox, tar_cat, tar_bbox, out);
}